// round 15
// baseline (speedup 1.0000x reference)
#include <cuda_runtime.h>
#include <cuda_fp16.h>
#include <cstdint>

#define BATCH 16
#define NQ    16384
#define CH    64
#define NKV   256
#define EPS   1e-5f
#define LOG2E 1.44269504088896340736f

// Scratch (device globals — no allocation allowed)
__device__ float  g_xconv[BATCH * NKV * CH];  // conv output [b*256+pos][c]
__device__ __half g_Gh[BATCH * 16384];        // G frags (pre-scaled 0.125*log2e)
__device__ __half g_VWh[BATCH * 16384];       // VW frags
__device__ float  g_sbias[BATCH * NKV];       // log2e*0.125*(bq . k_j)
__device__ uint2  g_Whf[65536];               // conv W, fp16 fragment-ordered
                                              // idx = ((kc*4+ks)*8+cg)*32+lane

__device__ __forceinline__ uint32_t pack_h2(float lo, float hi) {
    __half2 h = __floats2half2_rn(lo, hi);
    return *(uint32_t*)&h;
}

// fp16: D += A(16x16) @ B(16x8), fp32 accum
__device__ __forceinline__ void mma_f16(float* d, const uint32_t* a,
                                        uint32_t b0, uint32_t b1) {
    asm volatile(
        "mma.sync.aligned.m16n8k16.row.col.f32.f16.f16.f32 "
        "{%0,%1,%2,%3}, {%4,%5,%6,%7}, {%8,%9}, {%0,%1,%2,%3};"
        : "+f"(d[0]), "+f"(d[1]), "+f"(d[2]), "+f"(d[3])
        : "r"(a[0]), "r"(a[1]), "r"(a[2]), "r"(a[3]), "r"(b0), "r"(b1));
}

// ---------------------------------------------------------------------------
// Kernel W: one-time conv-weight -> fp16 fragment blob (512 KB, L2-resident).
// Thread = one uint2 frag word: (kc, ks, cg, lane); b0 = {W[k0+2lr][c],
// W[k0+2lr+1][c]}, b1 = same +8. convw layout [4096 k][64 c].
// ---------------------------------------------------------------------------
__global__ void __launch_bounds__(256, 1) wt_kernel(const float* __restrict__ convw)
{
    int tid  = blockIdx.x * 256 + threadIdx.x;      // 0..65535
    int lane = tid & 31;
    int cg   = (tid >> 5) & 7;
    int ks   = (tid >> 8) & 3;
    int kc   = tid >> 10;
    int lq = lane >> 2, lr = lane & 3;
    int c  = cg * 8 + lq;
    const float* p = convw + kc * 4096 + (ks * 16 + 2 * lr) * 64 + c;
    uint2 v;
    v.x = pack_h2(p[0],       p[64]);       // k0+2lr, k0+2lr+1
    v.y = pack_h2(p[8 * 64],  p[9 * 64]);   // k0+2lr+8, k0+2lr+9
    g_Whf[tid] = v;
}

// ---------------------------------------------------------------------------
// Kernel A: strided conv as GEMM via fp16 mma.sync — SMEM-FREE, BARRIER-FREE.
// grid 128 x 32 rows, 512 threads / 16 warps: warp = (2 rowgroups)x(8 colgrp).
// A-frags: float2 from global + pack (attention's X pattern, 8 KB/iter -> L1).
// B-frags: single LDG.64 from pre-fragmented g_Whf (L2-resident).
// Every k-iteration independent -> deep MLP, no STS/LDS/syncs at all.
// ---------------------------------------------------------------------------
__global__ void __launch_bounds__(512, 1) conv_kernel(
    const float* __restrict__ inp,
    const float* __restrict__ convb)
{
    int t = threadIdx.x, lane = t & 31, w = t >> 5;
    int lq = lane >> 2, lr = lane & 3;
    int rg16 = (w >> 3) * 16;      // 2 rowgroups of 16
    int cg   = w & 7;              // 8 col groups of 8

    // global base pointers for this thread's two A rows
    const float *x0, *x1;
    {
        int row0 = blockIdx.x * 32 + rg16 + lq;
        int b0 = row0 >> 8, patch0 = row0 & 255;
        x0 = inp + (((size_t)(b0 << 14) + ((patch0 >> 4) << 10) + ((patch0 & 15) << 3)) << 6);
        int row1 = row0 + 8;
        int b1 = row1 >> 8, patch1 = row1 & 255;
        x1 = inp + (((size_t)(b1 << 14) + ((patch1 >> 4) << 10) + ((patch1 & 15) << 3)) << 6);
    }
    const uint2* wb = g_Whf + cg * 32 + lane;   // + (kc*4+ks)*256

    float acc[4] = {};

#pragma unroll 4
    for (int kc = 0; kc < 64; ++kc) {
        int koff = (kc >> 3) * 8192 + (kc & 7) * 64;

        // B fragments (4 ksteps) — single LDG.64 each, L2/L1 hits
        uint2 bfr[4];
#pragma unroll
        for (int ks = 0; ks < 4; ++ks)
            bfr[ks] = wb[(kc * 4 + ks) * 256];

        // A fragments straight from global
        uint32_t afr[4][4];
#pragma unroll
        for (int ks = 0; ks < 4; ++ks) {
            int o = koff + ks * 16 + 2 * lr;
            float2 u0 = *(const float2*)&x0[o];
            float2 u1 = *(const float2*)&x1[o];
            float2 u2 = *(const float2*)&x0[o + 8];
            float2 u3 = *(const float2*)&x1[o + 8];
            afr[ks][0] = pack_h2(u0.x, u0.y);
            afr[ks][1] = pack_h2(u1.x, u1.y);
            afr[ks][2] = pack_h2(u2.x, u2.y);
            afr[ks][3] = pack_h2(u3.x, u3.y);
        }

#pragma unroll
        for (int ks = 0; ks < 4; ++ks)
            mma_f16(acc, afr[ks], bfr[ks].x, bfr[ks].y);
    }

    // epilogue
    int row0 = blockIdx.x * 32 + rg16 + lq;
    int c = cg * 8 + 2 * lr;
    float cb0 = convb[c], cb1 = convb[c + 1];
    *(float2*)&g_xconv[row0 * 64 + c] =
        make_float2(acc[0] + cb0, acc[1] + cb1);
    *(float2*)&g_xconv[(row0 + 8) * 64 + c] =
        make_float2(acc[2] + cb0, acc[3] + cb1);
}

// ---------------------------------------------------------------------------
// Kernel B: per kv position — LN, kv proj; emits FRAGMENT-ORDERED fp16 G/VW.
// G pre-scaled by 0.125*log2(e); sbias by 0.125*log2(e)  (softmax uses exp2).
// ---------------------------------------------------------------------------
__global__ void __launch_bounds__(256, 1) kv_kernel(
    const float* __restrict__ Wq,  const float* __restrict__ bq,
    const float* __restrict__ Wkv, const float* __restrict__ bkv,
    const float* __restrict__ Wo,
    const float* __restrict__ gamma, const float* __restrict__ beta)
{
    extern __shared__ float sm[];
    float* sWkv = sm;            // 8192
    float* sWo  = sm + 8192;     // 4096
    float* sWqT = sm + 12288;    // 64*65
    float* sx   = sm + 16448;
    float* sxn  = sm + 16512;
    float* skv  = sm + 16576;
    float* sgam = sm + 16704;
    float* sbet = sm + 16768;
    float* sbq  = sm + 16832;
    float* sbkv = sm + 16896;
    float* sstat= sm + 17024;

    int t = threadIdx.x;

#pragma unroll
    for (int it = 0; it < 8; ++it)
        ((float4*)sWkv)[it * 256 + t] = ((const float4*)Wkv)[it * 256 + t];
#pragma unroll
    for (int it = 0; it < 4; ++it)
        ((float4*)sWo)[it * 256 + t] = ((const float4*)Wo)[it * 256 + t];
#pragma unroll
    for (int it = 0; it < 4; ++it) {
        int f4i = it * 256 + t;
        int d = f4i >> 4, cc = (f4i & 15) * 4;
        float4 v = ((const float4*)Wq)[f4i];
        sWqT[(cc + 0) * 65 + d] = v.x;
        sWqT[(cc + 1) * 65 + d] = v.y;
        sWqT[(cc + 2) * 65 + d] = v.z;
        sWqT[(cc + 3) * 65 + d] = v.w;
    }
    if (t < 64)  { sgam[t] = gamma[t]; sbet[t] = beta[t]; sbq[t] = bq[t]; }
    if (t < 128) { sbkv[t] = bkv[t]; }
    __syncthreads();

    for (int p = 0; p < 8; ++p) {
        int j = blockIdx.x * 8 + p;
        if (t < 64) sx[t] = g_xconv[j * 64 + t];
        __syncthreads();

        if (t < 32) {
            float a = sx[t], b2 = sx[t + 32];
            float s = a + b2;
            float q = a * a + b2 * b2;
#pragma unroll
            for (int off = 16; off > 0; off >>= 1) {
                s += __shfl_xor_sync(0xffffffffu, s, off);
                q += __shfl_xor_sync(0xffffffffu, q, off);
            }
            if (t == 0) {
                float mean = s * (1.0f / 64.0f);
                sstat[0] = mean;
                sstat[1] = rsqrtf(q * (1.0f / 64.0f) - mean * mean + EPS);
            }
        }
        __syncthreads();
        if (t < 64)
            sxn[t] = (sx[t] - sstat[0]) * sstat[1] * sgam[t] + sbet[t];
        __syncthreads();

        if (t < 128) {
            float a = sbkv[t];
#pragma unroll 16
            for (int c = 0; c < 64; ++c)
                a += sxn[c] * sWkv[c * 128 + t];
            skv[t] = a;
        }
        __syncthreads();

        int b = j >> 8, pos = j & 255;
        if (t < 64) {
            float a = 0.0f;
#pragma unroll 16
            for (int c = 0; c < 64; ++c)
                a += sWqT[c * 65 + t] * skv[c];
            int nt = pos >> 3, lqj = pos & 7;
            int d = t, ks = d >> 4, dd = d & 15;
            int wrd = dd >> 3, lr = (dd >> 1) & 3, h = dd & 1;
            int idx = ((((b * 32 + nt) * 4 + ks) * 32 + lqj * 4 + lr) * 2 + wrd) * 2 + h;
            g_Gh[idx] = __float2half_rn(0.125f * LOG2E * a);
        } else if (t < 128) {
            int cc = t - 64;
            float a = 0.0f;
#pragma unroll 16
            for (int d = 0; d < 64; ++d)
                a += skv[64 + d] * sWo[d * 64 + cc];
            int ct = cc >> 3, lqc = cc & 7;
            int ks = pos >> 4, jj = pos & 15;
            int wrd = jj >> 3, lr = (jj >> 1) & 3, h = jj & 1;
            int idx = ((((b * 8 + ct) * 16 + ks) * 32 + lqc * 4 + lr) * 2 + wrd) * 2 + h;
            g_VWh[idx] = __float2half_rn(a);
        } else if (t == 128) {
            float a = 0.0f;
            for (int c = 0; c < 64; ++c)
                a += sbq[c] * skv[c];
            g_sbias[(b << 8) + pos] = 0.125f * LOG2E * a;
        }
        __syncthreads();
    }
}

// ---------------------------------------------------------------------------
// Kernel C: fp16 m16n8k16 attention (R9 structure); fragment-ordered B,
// register softmax (exp2, scales pre-folded), zero-shuffle P handoff.
// smem: sG 32KB, sVW 32KB, sbias 1KB, sbo 256B
// ---------------------------------------------------------------------------
#define AT_SMEM (32768 + 32768 + 1024 + 256)

__global__ void __launch_bounds__(256, 1) attn_kernel(
    const float* __restrict__ inp,
    const float* __restrict__ bo_g,
    float* __restrict__ out)
{
    extern __shared__ char smem[];
    uint2* sG    = (uint2*)smem;                    // 4096 uint2
    uint2* sVW   = (uint2*)(smem + 32768);          // 4096 uint2
    float* sbias = (float*)(smem + 65536);          // 256
    float* sbo   = (float*)(smem + 66560);          // 64

    int t = threadIdx.x, lane = t & 31, w = t >> 5;
    int lq = lane >> 2, lr = lane & 3;
    int m0 = w * 16;
    int b  = blockIdx.y;
    int n0 = blockIdx.x * 128;

    // ---- A-fragments of X from global, fp16 (k=64 -> 4 ksteps) ----
    uint32_t afr[4][4];
    {
        const float* x0 = inp + ((size_t)(b * NQ + n0 + m0 + lq)) * 64;
        const float* x1 = x0 + 8 * 64;
#pragma unroll
        for (int ks = 0; ks < 4; ++ks) {
            float2 u0 = *(const float2*)&x0[ks * 16 + 2 * lr];
            float2 u1 = *(const float2*)&x1[ks * 16 + 2 * lr];
            float2 u2 = *(const float2*)&x0[ks * 16 + 8 + 2 * lr];
            float2 u3 = *(const float2*)&x1[ks * 16 + 8 + 2 * lr];
            afr[ks][0] = pack_h2(u0.x, u0.y);
            afr[ks][1] = pack_h2(u1.x, u1.y);
            afr[ks][2] = pack_h2(u2.x, u2.y);
            afr[ks][3] = pack_h2(u3.x, u3.y);
        }
    }

    // ---- stage fragment blobs (linear copies) ----
    {
        const uint4* gG = (const uint4*)g_Gh + b * 2048;
        const uint4* gV = (const uint4*)g_VWh + b * 2048;
#pragma unroll
        for (int it = 0; it < 8; ++it) {
            ((uint4*)sG)[it * 256 + t]  = gG[it * 256 + t];
            ((uint4*)sVW)[it * 256 + t] = gV[it * 256 + t];
        }
    }
    if (t < 64) ((float4*)sbias)[t] = ((const float4*)(g_sbias + (b << 8)))[t];
    if (t < 16) ((float4*)sbo)[t]   = ((const float4*)bo_g)[t];
    __syncthreads();

    // ---- GEMM1: S = X @ G^T, 128 mma + 128 LDS.64 per warp ----
    float acc[32][4];
#pragma unroll
    for (int nt = 0; nt < 32; ++nt)
#pragma unroll
        for (int i = 0; i < 4; ++i) acc[nt][i] = 0.0f;

#pragma unroll
    for (int ks = 0; ks < 4; ++ks) {
#pragma unroll
        for (int nt = 0; nt < 32; ++nt) {
            uint2 bb = sG[(nt * 4 + ks) * 32 + lane];
            mma_f16(acc[nt], afr[ks], bb.x, bb.y);
        }
    }

    // ---- softmax in regs (log2 domain): +bias, row max, exp2, row sums ----
    float mx0 = -1e30f, mx1 = -1e30f;
#pragma unroll
    for (int nt = 0; nt < 32; ++nt) {
        int c = nt * 8 + 2 * lr;
        float bi0 = sbias[c], bi1 = sbias[c + 1];
        acc[nt][0] += bi0; acc[nt][1] += bi1;
        acc[nt][2] += bi0; acc[nt][3] += bi1;
        mx0 = fmaxf(mx0, fmaxf(acc[nt][0], acc[nt][1]));
        mx1 = fmaxf(mx1, fmaxf(acc[nt][2], acc[nt][3]));
    }
    mx0 = fmaxf(mx0, __shfl_xor_sync(0xffffffffu, mx0, 1));
    mx0 = fmaxf(mx0, __shfl_xor_sync(0xffffffffu, mx0, 2));
    mx1 = fmaxf(mx1, __shfl_xor_sync(0xffffffffu, mx1, 1));
    mx1 = fmaxf(mx1, __shfl_xor_sync(0xffffffffu, mx1, 2));

    float sum0 = 0.0f, sum1 = 0.0f;
#pragma unroll
    for (int nt = 0; nt < 32; ++nt) {
        float e0 = exp2f(acc[nt][0] - mx0);
        float e1 = exp2f(acc[nt][1] - mx0);
        float e2 = exp2f(acc[nt][2] - mx1);
        float e3 = exp2f(acc[nt][3] - mx1);
        sum0 += e0 + e1;
        sum1 += e2 + e3;
        acc[nt][0] = e0; acc[nt][1] = e1;
        acc[nt][2] = e2; acc[nt][3] = e3;
    }
    sum0 += __shfl_xor_sync(0xffffffffu, sum0, 1);
    sum0 += __shfl_xor_sync(0xffffffffu, sum0, 2);
    sum1 += __shfl_xor_sync(0xffffffffu, sum1, 1);
    sum1 += __shfl_xor_sync(0xffffffffu, sum1, 2);
    float rv0 = 1.0f / sum0;
    float rv1 = 1.0f / sum1;

    // ---- GEMM2: O = P @ VW^T; A-frags = packed own C-frags (no shfl) ----
    float acc2[8][4];
#pragma unroll
    for (int ct = 0; ct < 8; ++ct)
#pragma unroll
        for (int i = 0; i < 4; ++i) acc2[ct][i] = 0.0f;

#pragma unroll
    for (int ks = 0; ks < 16; ++ks) {
        uint32_t pa[4];
        pa[0] = pack_h2(acc[2 * ks][0],     acc[2 * ks][1]);
        pa[1] = pack_h2(acc[2 * ks][2],     acc[2 * ks][3]);
        pa[2] = pack_h2(acc[2 * ks + 1][0], acc[2 * ks + 1][1]);
        pa[3] = pack_h2(acc[2 * ks + 1][2], acc[2 * ks + 1][3]);
#pragma unroll
        for (int ct = 0; ct < 8; ++ct) {
            uint2 bb = sVW[(ct * 16 + ks) * 32 + lane];
            mma_f16(acc2[ct], pa, bb.x, bb.y);
        }
    }

    // ---- epilogue ----
    {
        size_t rg = (size_t)(b * NQ + n0 + m0 + lq) * 64;
#pragma unroll
        for (int ct = 0; ct < 8; ++ct) {
            int c = ct * 8 + 2 * lr;
            float2 o0 = make_float2(acc2[ct][0] * rv0 + sbo[c],
                                    acc2[ct][1] * rv0 + sbo[c + 1]);
            float2 o1 = make_float2(acc2[ct][2] * rv1 + sbo[c],
                                    acc2[ct][3] * rv1 + sbo[c + 1]);
            *(float2*)&out[rg + c] = o0;
            *(float2*)&out[rg + 8 * 64 + c] = o1;
        }
    }
}

// ---------------------------------------------------------------------------
extern "C" void kernel_launch(void* const* d_in, const int* in_sizes, int n_in,
                              void* d_out, int out_size)
{
    const float* inp   = (const float*)d_in[0];
    const float* Wq    = (const float*)d_in[1];
    const float* bq    = (const float*)d_in[2];
    const float* Wkv   = (const float*)d_in[3];
    const float* bkv   = (const float*)d_in[4];
    const float* Wo    = (const float*)d_in[5];
    const float* bo    = (const float*)d_in[6];
    const float* convw = (const float*)d_in[7];
    const float* convb = (const float*)d_in[8];
    const float* gamma = (const float*)d_in[9];
    const float* beta  = (const float*)d_in[10];
    float* out = (float*)d_out;

    const int smemB = 17026 * 4;
    cudaFuncSetAttribute(kv_kernel,   cudaFuncAttributeMaxDynamicSharedMemorySize, smemB);
    cudaFuncSetAttribute(attn_kernel, cudaFuncAttributeMaxDynamicSharedMemorySize, AT_SMEM);

    wt_kernel<<<256, 256>>>(convw);
    conv_kernel<<<128, 512>>>(inp, convb);
    kv_kernel<<<512, 256, smemB>>>(Wq, bq, Wkv, bkv, Wo, gamma, beta);
    attn_kernel<<<dim3(128, 16), 256, AT_SMEM>>>(inp, bo, out);
}

// round 17
// speedup vs baseline: 1.2944x; 1.2944x over previous
#include <cuda_runtime.h>
#include <cuda_fp16.h>
#include <cstdint>

#define BATCH 16
#define NQ    16384
#define CH    64
#define NKV   256
#define EPS   1e-5f
#define LOG2E 1.44269504088896340736f

// Scratch (device globals — no allocation allowed)
__device__ float  g_xcA[BATCH * NKV * CH];    // conv partial, k-half 0
__device__ float  g_xcB[BATCH * NKV * CH];    // conv partial, k-half 1
__device__ __half g_Gh[BATCH * 16384];        // G frags (pre-scaled 0.125*log2e)
__device__ __half g_VWh[BATCH * 16384];       // VW frags
__device__ float  g_sbias[BATCH * NKV];       // log2e*0.125*(bq . k_j)

__device__ __forceinline__ uint32_t to_tf32(float f) {
    uint32_t r; asm("cvt.rna.tf32.f32 %0, %1;" : "=r"(r) : "f"(f)); return r;
}
__device__ __forceinline__ uint32_t pack_h2(float lo, float hi) {
    __half2 h = __floats2half2_rn(lo, hi);
    return *(uint32_t*)&h;
}

// tf32: D += A(16x8) @ B(8x8)
__device__ __forceinline__ void mma_tf32(float* d, const uint32_t* a,
                                         uint32_t b0, uint32_t b1) {
    asm volatile(
        "mma.sync.aligned.m16n8k8.row.col.f32.tf32.tf32.f32 "
        "{%0,%1,%2,%3}, {%4,%5,%6,%7}, {%8,%9}, {%0,%1,%2,%3};"
        : "+f"(d[0]), "+f"(d[1]), "+f"(d[2]), "+f"(d[3])
        : "r"(a[0]), "r"(a[1]), "r"(a[2]), "r"(a[3]), "r"(b0), "r"(b1));
}
// fp16: D += A(16x16) @ B(16x8), fp32 accum
__device__ __forceinline__ void mma_f16(float* d, const uint32_t* a,
                                        uint32_t b0, uint32_t b1) {
    asm volatile(
        "mma.sync.aligned.m16n8k16.row.col.f32.f16.f16.f32 "
        "{%0,%1,%2,%3}, {%4,%5,%6,%7}, {%8,%9}, {%0,%1,%2,%3};"
        : "+f"(d[0]), "+f"(d[1]), "+f"(d[2]), "+f"(d[3])
        : "r"(a[0]), "r"(a[1]), "r"(a[2]), "r"(a[3]), "r"(b0), "r"(b1));
}

// ---------------------------------------------------------------------------
// Kernel A: strided conv as GEMM via tf32 mma.sync — R9 structure (register
// prefetch, SMEM tiles, 2 syncs/iter) + SPLIT-K over 2 halves.
// grid 256 = (128 row-blocks) x (2 k-halves); each block: 32 k-iters.
// 2 blocks/SM resident (89 regs, 27KB smem) -> doubled latency hiding.
// Partials summed (with convb) inside kv_kernel — deterministic, no atomics.
// ---------------------------------------------------------------------------
__global__ void __launch_bounds__(256, 2) conv_kernel(
    const float* __restrict__ inp,
    const float* __restrict__ convw)
{
    __shared__ float sA[32 * 68];
    __shared__ float sW[64 * 72];

    int rowblk = blockIdx.x & 127;
    int khalf  = blockIdx.x >> 7;
    int kbase  = khalf * 32;

    int t = threadIdx.x, lane = t & 31, w = t >> 5;
    int lq = lane >> 2, lr = lane & 3;
    int rg16 = (w >> 2) * 16;
    int cb   = (w & 3) * 16;

    int rarr[2], kkarr[2], rowbase[2];
#pragma unroll
    for (int it = 0; it < 2; ++it) {
        int f4i = it * 256 + t;
        int r   = f4i >> 4;
        int kk  = (f4i & 15) * 4;
        int rg  = rowblk * 32 + r;
        int b   = rg >> 8;
        int patch = rg & 255;
        int pi  = patch >> 4, pj = patch & 15;
        rarr[it]  = r;
        kkarr[it] = kk;
        rowbase[it] = (b << 14) + (pi << 10) + (pj << 3);
    }
    int kinarr[4], c4arr[4];
#pragma unroll
    for (int it = 0; it < 4; ++it) {
        int f4i = it * 256 + t;
        kinarr[it] = f4i >> 4;
        c4arr[it]  = (f4i & 15) * 4;
    }

    float acc[2][4] = {};
    float4 pa[2], pw[4];

    // prefetch first iter of this k-half
    {
        int di = kbase >> 3, dj = kbase & 7;
#pragma unroll
        for (int it = 0; it < 2; ++it)
            pa[it] = *(const float4*)&inp[((rowbase[it] + di * 128 + dj) << 6) + kkarr[it]];
#pragma unroll
        for (int it = 0; it < 4; ++it)
            pw[it] = *(const float4*)&convw[(kbase << 12) + kinarr[it] * 64 + c4arr[it]];
    }

    for (int kc = kbase; kc < kbase + 32; ++kc) {
#pragma unroll
        for (int it = 0; it < 2; ++it) {
            float4 v = pa[it];
            uint4 u = make_uint4(to_tf32(v.x), to_tf32(v.y), to_tf32(v.z), to_tf32(v.w));
            *(uint4*)&sA[rarr[it] * 68 + kkarr[it]] = u;
        }
#pragma unroll
        for (int it = 0; it < 4; ++it) {
            float4 v = pw[it];
            uint4 u = make_uint4(to_tf32(v.x), to_tf32(v.y), to_tf32(v.z), to_tf32(v.w));
            *(uint4*)&sW[kinarr[it] * 72 + c4arr[it]] = u;
        }
        __syncthreads();

        if (kc + 1 < kbase + 32) {
            int kn = kc + 1, di = kn >> 3, dj = kn & 7;
#pragma unroll
            for (int it = 0; it < 2; ++it)
                pa[it] = *(const float4*)&inp[((rowbase[it] + di * 128 + dj) << 6) + kkarr[it]];
#pragma unroll
            for (int it = 0; it < 4; ++it)
                pw[it] = *(const float4*)&convw[(kn << 12) + kinarr[it] * 64 + c4arr[it]];
        }

#pragma unroll
        for (int k = 0; k < 8; ++k) {
            uint32_t a[4];
            a[0] = __float_as_uint(sA[(rg16 + lq) * 68 + k * 8 + lr]);
            a[1] = __float_as_uint(sA[(rg16 + 8 + lq) * 68 + k * 8 + lr]);
            a[2] = __float_as_uint(sA[(rg16 + lq) * 68 + k * 8 + lr + 4]);
            a[3] = __float_as_uint(sA[(rg16 + 8 + lq) * 68 + k * 8 + lr + 4]);
#pragma unroll
            for (int nb = 0; nb < 2; ++nb) {
                uint32_t b0 = __float_as_uint(sW[(k * 8 + lr) * 72 + cb + nb * 8 + lq]);
                uint32_t b1 = __float_as_uint(sW[(k * 8 + lr + 4) * 72 + cb + nb * 8 + lq]);
                mma_tf32(acc[nb], a, b0, b1);
            }
        }
        __syncthreads();
    }

    float* dst = khalf ? g_xcB : g_xcA;
    int row0 = rowblk * 32 + rg16 + lq;
#pragma unroll
    for (int nb = 0; nb < 2; ++nb) {
        int c = cb + nb * 8 + 2 * lr;
        *(float2*)&dst[row0 * 64 + c]       = make_float2(acc[nb][0], acc[nb][1]);
        *(float2*)&dst[(row0 + 8) * 64 + c] = make_float2(acc[nb][2], acc[nb][3]);
    }
}

// ---------------------------------------------------------------------------
// Kernel B: per kv position — sums conv partials + convb, LN, kv proj;
// emits FRAGMENT-ORDERED fp16 G/VW. G/sbias pre-scaled by 0.125*log2(e).
// ---------------------------------------------------------------------------
__global__ void __launch_bounds__(256, 1) kv_kernel(
    const float* __restrict__ Wq,  const float* __restrict__ bq,
    const float* __restrict__ Wkv, const float* __restrict__ bkv,
    const float* __restrict__ Wo,
    const float* __restrict__ gamma, const float* __restrict__ beta,
    const float* __restrict__ convb)
{
    extern __shared__ float sm[];
    float* sWkv = sm;            // 8192
    float* sWo  = sm + 8192;     // 4096
    float* sWqT = sm + 12288;    // 64*65
    float* sx   = sm + 16448;
    float* sxn  = sm + 16512;
    float* skv  = sm + 16576;
    float* sgam = sm + 16704;
    float* sbet = sm + 16768;
    float* sbq  = sm + 16832;
    float* sbkv = sm + 16896;
    float* sstat= sm + 17024;    // 2
    float* scvb = sm + 17028;    // 64

    int t = threadIdx.x;

#pragma unroll
    for (int it = 0; it < 8; ++it)
        ((float4*)sWkv)[it * 256 + t] = ((const float4*)Wkv)[it * 256 + t];
#pragma unroll
    for (int it = 0; it < 4; ++it)
        ((float4*)sWo)[it * 256 + t] = ((const float4*)Wo)[it * 256 + t];
#pragma unroll
    for (int it = 0; it < 4; ++it) {
        int f4i = it * 256 + t;
        int d = f4i >> 4, cc = (f4i & 15) * 4;
        float4 v = ((const float4*)Wq)[f4i];
        sWqT[(cc + 0) * 65 + d] = v.x;
        sWqT[(cc + 1) * 65 + d] = v.y;
        sWqT[(cc + 2) * 65 + d] = v.z;
        sWqT[(cc + 3) * 65 + d] = v.w;
    }
    if (t < 64)  { sgam[t] = gamma[t]; sbet[t] = beta[t]; sbq[t] = bq[t]; scvb[t] = convb[t]; }
    if (t < 128) { sbkv[t] = bkv[t]; }
    __syncthreads();

    for (int p = 0; p < 8; ++p) {
        int j = blockIdx.x * 8 + p;
        if (t < 64) sx[t] = g_xcA[j * 64 + t] + g_xcB[j * 64 + t] + scvb[t];
        __syncthreads();

        if (t < 32) {
            float a = sx[t], b2 = sx[t + 32];
            float s = a + b2;
            float q = a * a + b2 * b2;
#pragma unroll
            for (int off = 16; off > 0; off >>= 1) {
                s += __shfl_xor_sync(0xffffffffu, s, off);
                q += __shfl_xor_sync(0xffffffffu, q, off);
            }
            if (t == 0) {
                float mean = s * (1.0f / 64.0f);
                sstat[0] = mean;
                sstat[1] = rsqrtf(q * (1.0f / 64.0f) - mean * mean + EPS);
            }
        }
        __syncthreads();
        if (t < 64)
            sxn[t] = (sx[t] - sstat[0]) * sstat[1] * sgam[t] + sbet[t];
        __syncthreads();

        if (t < 128) {
            float a = sbkv[t];
#pragma unroll 16
            for (int c = 0; c < 64; ++c)
                a += sxn[c] * sWkv[c * 128 + t];
            skv[t] = a;
        }
        __syncthreads();

        int b = j >> 8, pos = j & 255;
        if (t < 64) {
            float a = 0.0f;
#pragma unroll 16
            for (int c = 0; c < 64; ++c)
                a += sWqT[c * 65 + t] * skv[c];
            int nt = pos >> 3, lqj = pos & 7;
            int d = t, ks = d >> 4, dd = d & 15;
            int wrd = dd >> 3, lr = (dd >> 1) & 3, h = dd & 1;
            int idx = ((((b * 32 + nt) * 4 + ks) * 32 + lqj * 4 + lr) * 2 + wrd) * 2 + h;
            g_Gh[idx] = __float2half_rn(0.125f * LOG2E * a);
        } else if (t < 128) {
            int cc = t - 64;
            float a = 0.0f;
#pragma unroll 16
            for (int d = 0; d < 64; ++d)
                a += skv[64 + d] * sWo[d * 64 + cc];
            int ct = cc >> 3, lqc = cc & 7;
            int ks = pos >> 4, jj = pos & 15;
            int wrd = jj >> 3, lr = (jj >> 1) & 3, h = jj & 1;
            int idx = ((((b * 8 + ct) * 16 + ks) * 32 + lqc * 4 + lr) * 2 + wrd) * 2 + h;
            g_VWh[idx] = __float2half_rn(a);
        } else if (t == 128) {
            float a = 0.0f;
            for (int c = 0; c < 64; ++c)
                a += sbq[c] * skv[c];
            g_sbias[(b << 8) + pos] = 0.125f * LOG2E * a;
        }
        __syncthreads();
    }
}

// ---------------------------------------------------------------------------
// Kernel C: fp16 m16n8k16 attention, FLASH-CHUNKED over j (2 x 128) with
// online softmax — halves the S register footprint (192 -> ~128 regs) so
// 2 blocks/SM are resident. No extra barriers (rescale is per-warp).
// smem: sG 32KB, sVW 32KB, sbias 1KB, sbo 256B
// ---------------------------------------------------------------------------
#define AT_SMEM (32768 + 32768 + 1024 + 256)

__global__ void __launch_bounds__(256, 2) attn_kernel(
    const float* __restrict__ inp,
    const float* __restrict__ bo_g,
    float* __restrict__ out)
{
    extern __shared__ char smem[];
    uint2* sG    = (uint2*)smem;                    // 4096 uint2
    uint2* sVW   = (uint2*)(smem + 32768);          // 4096 uint2
    float* sbias = (float*)(smem + 65536);          // 256
    float* sbo   = (float*)(smem + 66560);          // 64

    int t = threadIdx.x, lane = t & 31, w = t >> 5;
    int lq = lane >> 2, lr = lane & 3;
    int m0 = w * 16;
    int b  = blockIdx.y;
    int n0 = blockIdx.x * 128;

    // ---- A-fragments of X from global, fp16 (k=64 -> 4 ksteps) ----
    uint32_t afr[4][4];
    {
        const float* x0 = inp + ((size_t)(b * NQ + n0 + m0 + lq)) * 64;
        const float* x1 = x0 + 8 * 64;
#pragma unroll
        for (int ks = 0; ks < 4; ++ks) {
            float2 u0 = *(const float2*)&x0[ks * 16 + 2 * lr];
            float2 u1 = *(const float2*)&x1[ks * 16 + 2 * lr];
            float2 u2 = *(const float2*)&x0[ks * 16 + 8 + 2 * lr];
            float2 u3 = *(const float2*)&x1[ks * 16 + 8 + 2 * lr];
            afr[ks][0] = pack_h2(u0.x, u0.y);
            afr[ks][1] = pack_h2(u1.x, u1.y);
            afr[ks][2] = pack_h2(u2.x, u2.y);
            afr[ks][3] = pack_h2(u3.x, u3.y);
        }
    }

    // ---- stage fragment blobs (linear copies) ----
    {
        const uint4* gG = (const uint4*)g_Gh + b * 2048;
        const uint4* gV = (const uint4*)g_VWh + b * 2048;
#pragma unroll
        for (int it = 0; it < 8; ++it) {
            ((uint4*)sG)[it * 256 + t]  = gG[it * 256 + t];
            ((uint4*)sVW)[it * 256 + t] = gV[it * 256 + t];
        }
    }
    if (t < 64) ((float4*)sbias)[t] = ((const float4*)(g_sbias + (b << 8)))[t];
    if (t < 16) ((float4*)sbo)[t]   = ((const float4*)bo_g)[t];
    __syncthreads();

    // ---- flash-chunked mainloop: j in two halves of 128 ----
    float acc2[8][4];
#pragma unroll
    for (int ct = 0; ct < 8; ++ct)
#pragma unroll
        for (int i = 0; i < 4; ++i) acc2[ct][i] = 0.0f;

    float rm0 = -1e30f, rm1 = -1e30f;    // running row max (log2 domain)
    float rs0 = 0.0f,  rs1 = 0.0f;       // running per-lane sums

#pragma unroll
    for (int ch = 0; ch < 2; ++ch) {
        // GEMM1 chunk: S(16 rows x 128 cols)
        float acc[16][4];
#pragma unroll
        for (int nt = 0; nt < 16; ++nt)
#pragma unroll
            for (int i = 0; i < 4; ++i) acc[nt][i] = 0.0f;

#pragma unroll
        for (int ks = 0; ks < 4; ++ks) {
#pragma unroll
            for (int nt = 0; nt < 16; ++nt) {
                uint2 bb = sG[((ch * 16 + nt) * 4 + ks) * 32 + lane];
                mma_f16(acc[nt], afr[ks], bb.x, bb.y);
            }
        }

        // bias + local max
        float lm0 = -1e30f, lm1 = -1e30f;
#pragma unroll
        for (int nt = 0; nt < 16; ++nt) {
            int c = (ch * 16 + nt) * 8 + 2 * lr;
            float bi0 = sbias[c], bi1 = sbias[c + 1];
            acc[nt][0] += bi0; acc[nt][1] += bi1;
            acc[nt][2] += bi0; acc[nt][3] += bi1;
            lm0 = fmaxf(lm0, fmaxf(acc[nt][0], acc[nt][1]));
            lm1 = fmaxf(lm1, fmaxf(acc[nt][2], acc[nt][3]));
        }
        lm0 = fmaxf(lm0, __shfl_xor_sync(0xffffffffu, lm0, 1));
        lm0 = fmaxf(lm0, __shfl_xor_sync(0xffffffffu, lm0, 2));
        lm1 = fmaxf(lm1, __shfl_xor_sync(0xffffffffu, lm1, 1));
        lm1 = fmaxf(lm1, __shfl_xor_sync(0xffffffffu, lm1, 2));

        // online rescale
        float nm0 = fmaxf(rm0, lm0), nm1 = fmaxf(rm1, lm1);
        float f0 = exp2f(rm0 - nm0), f1 = exp2f(rm1 - nm1);
        rs0 *= f0; rs1 *= f1;
#pragma unroll
        for (int ct = 0; ct < 8; ++ct) {
            acc2[ct][0] *= f0; acc2[ct][1] *= f0;
            acc2[ct][2] *= f1; acc2[ct][3] *= f1;
        }
        rm0 = nm0; rm1 = nm1;

        // exp2, per-lane sums, pack P in place (acc[nt][0..1] <- h2 pairs)
#pragma unroll
        for (int nt = 0; nt < 16; ++nt) {
            float e0 = exp2f(acc[nt][0] - nm0);
            float e1 = exp2f(acc[nt][1] - nm0);
            float e2 = exp2f(acc[nt][2] - nm1);
            float e3 = exp2f(acc[nt][3] - nm1);
            rs0 += e0 + e1;
            rs1 += e2 + e3;
            acc[nt][0] = __uint_as_float(pack_h2(e0, e1));
            acc[nt][1] = __uint_as_float(pack_h2(e2, e3));
        }

        // GEMM2 partial: this chunk's 8 ksteps
#pragma unroll
        for (int ks = 0; ks < 8; ++ks) {
            uint32_t pa[4];
            pa[0] = __float_as_uint(acc[2 * ks][0]);
            pa[1] = __float_as_uint(acc[2 * ks][1]);
            pa[2] = __float_as_uint(acc[2 * ks + 1][0]);
            pa[3] = __float_as_uint(acc[2 * ks + 1][1]);
#pragma unroll
            for (int ct = 0; ct < 8; ++ct) {
                uint2 bb = sVW[(ct * 16 + ch * 8 + ks) * 32 + lane];
                mma_f16(acc2[ct], pa, bb.x, bb.y);
            }
        }
    }

    // final row sums (quad reduce)
    rs0 += __shfl_xor_sync(0xffffffffu, rs0, 1);
    rs0 += __shfl_xor_sync(0xffffffffu, rs0, 2);
    rs1 += __shfl_xor_sync(0xffffffffu, rs1, 1);
    rs1 += __shfl_xor_sync(0xffffffffu, rs1, 2);
    float rv0 = 1.0f / rs0;
    float rv1 = 1.0f / rs1;

    // ---- epilogue ----
    {
        size_t rg = (size_t)(b * NQ + n0 + m0 + lq) * 64;
#pragma unroll
        for (int ct = 0; ct < 8; ++ct) {
            int c = ct * 8 + 2 * lr;
            float2 o0 = make_float2(acc2[ct][0] * rv0 + sbo[c],
                                    acc2[ct][1] * rv0 + sbo[c + 1]);
            float2 o1 = make_float2(acc2[ct][2] * rv1 + sbo[c],
                                    acc2[ct][3] * rv1 + sbo[c + 1]);
            *(float2*)&out[rg + c] = o0;
            *(float2*)&out[rg + 8 * 64 + c] = o1;
        }
    }
}

// ---------------------------------------------------------------------------
extern "C" void kernel_launch(void* const* d_in, const int* in_sizes, int n_in,
                              void* d_out, int out_size)
{
    const float* inp   = (const float*)d_in[0];
    const float* Wq    = (const float*)d_in[1];
    const float* bq    = (const float*)d_in[2];
    const float* Wkv   = (const float*)d_in[3];
    const float* bkv   = (const float*)d_in[4];
    const float* Wo    = (const float*)d_in[5];
    const float* bo    = (const float*)d_in[6];
    const float* convw = (const float*)d_in[7];
    const float* convb = (const float*)d_in[8];
    const float* gamma = (const float*)d_in[9];
    const float* beta  = (const float*)d_in[10];
    float* out = (float*)d_out;

    const int smemB = 17092 * 4;
    cudaFuncSetAttribute(kv_kernel,   cudaFuncAttributeMaxDynamicSharedMemorySize, smemB);
    cudaFuncSetAttribute(attn_kernel, cudaFuncAttributeMaxDynamicSharedMemorySize, AT_SMEM);

    conv_kernel<<<256, 256>>>(inp, convw);
    kv_kernel<<<512, 256, smemB>>>(Wq, bq, Wkv, bkv, Wo, gamma, beta, convb);
    attn_kernel<<<dim3(128, 16), 256, AT_SMEM>>>(inp, bo, out);
}